// round 14
// baseline (speedup 1.0000x reference)
#include <cuda_runtime.h>
#include <cstdint>

#define HH 64
#define WW 64
#define CI 256
#define CO 256
#define BB 8
#define KK 9
#define CK (CI*KK)      // 2304
#define NCHUNK 72
#define ASTR 40         // k_off smem stride

// k_gemm layout: m128 x n128 tile, both operands stride 136 (136%32==8 -> conflict-free)
#define ASTRIDE 136
#define ABYTES  (32*ASTRIDE*4)          // 17408
#define STG2    (2*ABYTES)              // A+B per stage: 34816
#define GEMM_SMEM (3*STG2)              // 104448 (2 CTAs/SM fit in 227KB)

// ---------------- scratch (device globals; no allocation) ----------------
__device__ float  g_owt[CK*32];              // tf32 offset/mod weights, [ck][oc-pad32]
__device__ float  g_wtT[CK*CO];              // tf32 reg_w transposed: [ck][o]
__device__ uint2  g_idx[BB*HH*KK*WW];        // packed 4 x u16 corner indices (y*64+x)
__device__ float4 g_wgt[BB*HH*KK*WW];        // 4 bilinear wgts * mask * valid
__device__ float  g_val[(size_t)BB*CK*4096]; // gathered A: [b][ck][s], tf32

// ---------------- helpers ----------------
__device__ __forceinline__ float to_tf32(float x) {
    float r; asm("cvt.rna.tf32.f32 %0, %1;" : "=f"(r) : "f"(x)); return r;
}
__device__ __forceinline__ void mma_tf32(float* d,
    uint32_t a0, uint32_t a1, uint32_t a2, uint32_t a3, uint32_t b0, uint32_t b1) {
    asm volatile("mma.sync.aligned.m16n8k8.row.col.f32.tf32.tf32.f32 "
        "{%0,%1,%2,%3}, {%4,%5,%6,%7}, {%8,%9}, {%0,%1,%2,%3};"
        : "+f"(d[0]), "+f"(d[1]), "+f"(d[2]), "+f"(d[3])
        : "r"(a0), "r"(a1), "r"(a2), "r"(a3), "r"(b0), "r"(b1));
}
__device__ __forceinline__ int div9(int kg) { return (kg * 7282) >> 16; }   // kg < 2304
__device__ __forceinline__ uint32_t smem_u32(const void* p) {
    uint32_t a;
    asm("{ .reg .u64 t; cvta.to.shared.u64 t, %1; cvt.u32.u64 %0, t; }" : "=r"(a) : "l"(p));
    return a;
}
#define CP_ASYNC16(sa, ga) asm volatile("cp.async.cg.shared.global [%0], [%1], 16;" :: "r"(sa), "l"(ga))
#define CP_COMMIT()        asm volatile("cp.async.commit_group;" ::: "memory")
#define CP_WAIT1()         asm volatile("cp.async.wait_group 1;" ::: "memory")
#define CP_WAIT0()         asm volatile("cp.async.wait_group 0;" ::: "memory")

// ---------------- kernel 0: weight prep ----------------
__global__ __launch_bounds__(256) void k_prep(
    const float* __restrict__ reg_w,
    const float* __restrict__ off_w,
    const float* __restrict__ mod_w)
{
    int i = blockIdx.x * 256 + threadIdx.x;
    if (i < CK*CO) {                       // i = ck*256 + o
        int o = i & 255, ck = i >> 8;
        g_wtT[i] = to_tf32(reg_w[o * CK + ck]);
    }
    if (i < CK*32) {
        int oc = i & 31, ck = i >> 5;
        float v = 0.f;
        if (oc < 18)      v = off_w[oc * CK + ck];
        else if (oc < 27) v = mod_w[(oc - 18) * CK + ck];
        g_owt[i] = to_tf32(v);
    }
}

// ---------------- kernel 1: offset/mod conv (tf32 MMA) + sampling metadata ----
__global__ __launch_bounds__(256) void k_off(
    const float* __restrict__ x,
    const float* __restrict__ off_b,
    const float* __restrict__ mod_b)
{
    __shared__ float xs[5*6*68];
    __shared__ float wb[32*ASTR];
    __shared__ float sD[256*28];

    const int t = threadIdx.x;
    const int h0 = blockIdx.x * 4, b = blockIdx.y;
    const int lane = t & 31, wid = t >> 5;
    const int q = lane >> 2, c2 = lane & 3;

    const float* xb = x + (size_t)b * CI * HH * WW;

    float acc[2][4][4];
    #pragma unroll
    for (int a = 0; a < 2; a++)
        #pragma unroll
        for (int c = 0; c < 4; c++)
            #pragma unroll
            for (int u = 0; u < 4; u++) acc[a][c][u] = 0.f;

    for (int i = 0; i < NCHUNK; i++) {
        __syncthreads();
        const int cbase = div9(32 * i);
        #pragma unroll
        for (int j = 0; j < 8; j++) {
            int e = t + j * 256;
            if (e < 5*408) {
                int slot = e / 408, rem = e - slot * 408;
                int row6 = rem / 68, col = rem - row6 * 68;
                int c = cbase + slot;
                int y = h0 - 1 + row6, xc = col - 1;
                float v = 0.f;
                if (c < CI && y >= 0 && y < HH && xc >= 0 && xc < WW)
                    v = xb[((size_t)c * HH + y) * WW + xc];
                xs[e] = v;
            }
        }
        #pragma unroll
        for (int j = 0; j < 4; j++) {
            int e = t + j * 256;
            int k = e >> 5, oc = e & 31;
            wb[k * ASTR + oc] = g_owt[(i * 32 + k) * 32 + oc];
        }
        __syncthreads();

        int aoff[8];
        #pragma unroll
        for (int u = 0; u < 8; u++) {
            int kv = (u >> 1) * 8 + c2 + (u & 1) * 4;
            int kg = i * 32 + kv;
            int c = div9(kg), tap = kg - c * 9;
            int ky = (tap * 11) >> 5, kx = tap - 3 * ky;
            aoff[u] = (c - cbase) * 408 + ky * 68 + kx;
        }

        #pragma unroll
        for (int ks = 0; ks < 4; ks++) {
            uint32_t af[2][4];
            #pragma unroll
            for (int mi = 0; mi < 2; mi++) {
                int m0 = wid * 32 + mi * 16;
                int base = (m0 >> 6) * 68 + (m0 & 63) + q;
                af[mi][0] = __float_as_uint(to_tf32(xs[aoff[2*ks]     + base]));
                af[mi][1] = __float_as_uint(to_tf32(xs[aoff[2*ks]     + base + 8]));
                af[mi][2] = __float_as_uint(to_tf32(xs[aoff[2*ks + 1] + base]));
                af[mi][3] = __float_as_uint(to_tf32(xs[aoff[2*ks + 1] + base + 8]));
            }
            uint32_t bf[4][2];
            #pragma unroll
            for (int nj = 0; nj < 4; nj++) {
                int n = nj * 8 + q;
                bf[nj][0] = __float_as_uint(wb[(8*ks + c2)     * ASTR + n]);
                bf[nj][1] = __float_as_uint(wb[(8*ks + c2 + 4) * ASTR + n]);
            }
            #pragma unroll
            for (int mi = 0; mi < 2; mi++)
                #pragma unroll
                for (int nj = 0; nj < 4; nj++)
                    mma_tf32(acc[mi][nj], af[mi][0], af[mi][1], af[mi][2], af[mi][3],
                             bf[nj][0], bf[nj][1]);
        }
    }

    __syncthreads();
    #pragma unroll
    for (int mi = 0; mi < 2; mi++) {
        #pragma unroll
        for (int nj = 0; nj < 4; nj++) {
            int m = wid * 32 + mi * 16 + q;
            int oc = nj * 8 + 2 * c2;
            if (oc < 28) {
                float b0 = (oc < 18) ? off_b[oc] : ((oc < 27) ? mod_b[oc - 18] : 0.f);
                int oc1 = oc + 1;
                float b1 = (oc1 < 18) ? off_b[oc1] : ((oc1 < 27) ? mod_b[oc1 - 18] : 0.f);
                sD[m * 28 + oc]           = acc[mi][nj][0] + b0;
                if (oc1 < 28) sD[m * 28 + oc1] = acc[mi][nj][1] + b1;
                sD[(m + 8) * 28 + oc]     = acc[mi][nj][2] + b0;
                if (oc1 < 28) sD[(m + 8) * 28 + oc1] = acc[mi][nj][3] + b1;
            }
        }
    }
    __syncthreads();

    #pragma unroll
    for (int j = 0; j < 9; j++) {
        int e = t + j * 256;
        int r = e / 576, rem = e - r * 576;
        int k = rem >> 6, s = rem & 63;
        int m = r * 64 + s;
        float oy = sD[m * 28 + 2*k];
        float ox = sD[m * 28 + 2*k + 1];
        float mm = sD[m * 28 + 18 + k];
        oy = fminf(fmaxf(oy, -16.f), 16.f);
        ox = fminf(fmaxf(ox, -16.f), 16.f);
        mm = 1.f / (1.f + expf(-mm));
        float py = oy + (float)(k / 3) + (float)(h0 + r - 1);
        float px = ox + (float)(k % 3) + (float)(s - 1);
        float y0f = floorf(py), x0f = floorf(px);
        float ly = py - y0f, lx = px - x0f;
        int y0 = (int)y0f, x0 = (int)x0f;
        int y1 = y0 + 1, x1 = x0 + 1;
        float vy0 = (y0 >= 0 && y0 < HH) ? 1.f : 0.f;
        float vy1 = (y1 >= 0 && y1 < HH) ? 1.f : 0.f;
        float vx0 = (x0 >= 0 && x0 < WW) ? 1.f : 0.f;
        float vx1 = (x1 >= 0 && x1 < WW) ? 1.f : 0.f;
        unsigned iy0 = min(max(y0, 0), HH-1), iy1 = min(max(y1, 0), HH-1);
        unsigned ix0 = min(max(x0, 0), WW-1), ix1 = min(max(x1, 0), WW-1);
        float w00 = (1.f-ly)*(1.f-lx)*mm*vy0*vx0;
        float w01 = (1.f-ly)*     lx *mm*vy0*vx1;
        float w10 =      ly *(1.f-lx)*mm*vy1*vx0;
        float w11 =      ly *     lx *mm*vy1*vx1;
        size_t g = ((size_t)(b * HH + h0 + r) * KK + k) * WW + s;
        g_idx[g] = make_uint2((iy0*WW+ix0) | ((iy0*WW+ix1) << 16),
                              (iy1*WW+ix0) | ((iy1*WW+ix1) << 16));
        g_wgt[g] = make_float4(w00, w01, w10, w11);
    }
}

// ---------------- kernel 2: smem-plane gather -> g_val ----------------
// CTA per (4 h-rows, c-half, b): per channel stage 64x64 plane, gather via LDS
__global__ __launch_bounds__(256, 2) void k_gather(const float* __restrict__ x)
{
    __shared__ float plane[4096];

    const int t = threadIdx.x;
    const int h0 = blockIdx.x * 4;
    const int c0 = blockIdx.y * 128;        // channel half
    const int b  = blockIdx.z;
    const int r = t >> 6, w = t & 63;

    uint2  mid[9];
    float4 mwg[9];
    #pragma unroll
    for (int tap = 0; tap < 9; tap++) {
        size_t g = ((size_t)(b * HH + h0 + r) * KK + tap) * WW + w;
        mid[tap] = g_idx[g];
        mwg[tap] = g_wgt[g];
    }

    const float4* xb4 = (const float4*)(x + (size_t)b * CI * HH * WW);
    float* vb = g_val + (size_t)b * CK * 4096;
    const int sbase = (h0 + r) * 64 + w;

    float4 pre[4];
    #pragma unroll
    for (int u = 0; u < 4; u++) pre[u] = xb4[(size_t)c0 * 1024 + t + u * 256];

    for (int ci = 0; ci < 128; ci++) {
        const int c = c0 + ci;
        __syncthreads();
        #pragma unroll
        for (int u = 0; u < 4; u++) ((float4*)plane)[t + u * 256] = pre[u];
        __syncthreads();
        if (ci + 1 < 128) {
            const float4* xn = xb4 + (size_t)(c + 1) * 1024;
            #pragma unroll
            for (int u = 0; u < 4; u++) pre[u] = xn[t + u * 256];
        }
        #pragma unroll
        for (int tap = 0; tap < 9; tap++) {
            uint2 id = mid[tap];
            float4 wg = mwg[tap];
            float v = wg.x * plane[id.x & 0xFFFF] + wg.y * plane[id.x >> 16]
                    + wg.z * plane[id.y & 0xFFFF] + wg.w * plane[id.y >> 16];
            vb[(size_t)(c * 9 + tap) * 4096 + sbase] = to_tf32(v);
        }
    }
}

// ---------------- kernel 3: dense tf32 GEMM v3 ----------------
// CTA per (m-tile 128 s, o-half 128, b): 256 thr, 2 CTAs/SM, 3-stage cp.async
__global__ __launch_bounds__(256, 2) void k_gemm(float* __restrict__ out)
{
    extern __shared__ char smem[];

    const int t  = threadIdx.x;
    const int mt = blockIdx.x;          // 0..31
    const int bo = blockIdx.y * 128;    // o half
    const int b  = blockIdx.z;          // 0..7
    const int lane = t & 31, wid = t >> 5;
    const int q = lane >> 2, c2 = lane & 3;
    const int mq = wid & 3, nq = wid >> 2;    // warp tile: m32 x n64 (nq: 0..1)

    const int rowT = t >> 3, lane8 = t & 7;   // staging: 32 rows x 8 lanes x 16 floats
    const float* Ag = g_val + (size_t)b * CK * 4096 + mt * 128;
    const uint32_t sbase = smem_u32(smem);
    const uint32_t daBase = sbase + rowT * (ASTRIDE*4) + lane8 * 64;
    const uint32_t dbBase = sbase + ABYTES + rowT * (ASTRIDE*4) + lane8 * 64;

    float acc[2][8][4];
    #pragma unroll
    for (int a = 0; a < 2; a++)
        #pragma unroll
        for (int c = 0; c < 8; c++)
            #pragma unroll
            for (int u = 0; u < 4; u++) acc[a][c][u] = 0.f;

    auto produce = [&](int j) {
        const uint32_t soff = (uint32_t)(j % 3) * STG2;
        const float* ga = Ag + (size_t)(j * 32 + rowT) * 4096 + lane8 * 16;
        const float* gb = g_wtT + (size_t)(j * 32 + rowT) * 256 + bo + lane8 * 16;
        uint32_t da = daBase + soff;
        uint32_t db = dbBase + soff;
        #pragma unroll
        for (int u = 0; u < 4; u++) {
            CP_ASYNC16(da + u * 16, ga + u * 4);
            CP_ASYNC16(db + u * 16, gb + u * 4);
        }
    };

    produce(0); CP_COMMIT();
    produce(1); CP_COMMIT();

    for (int i = 0; i < NCHUNK; i++) {
        if (i + 1 < NCHUNK) CP_WAIT1(); else CP_WAIT0();
        __syncthreads();

        const float* Ab = (const float*)(smem + (i % 3) * STG2);
        const float* Bb = (const float*)(smem + (i % 3) * STG2 + ABYTES);
        #pragma unroll
        for (int ks = 0; ks < 4; ks++) {
            const int kr = ks * 8 + c2;
            uint32_t af[2][4];
            #pragma unroll
            for (int mi = 0; mi < 2; mi++) {
                int m0 = mq * 32 + mi * 16 + q;
                af[mi][0] = __float_as_uint(Ab[kr * ASTRIDE + m0]);
                af[mi][1] = __float_as_uint(Ab[kr * ASTRIDE + m0 + 8]);
                af[mi][2] = __float_as_uint(Ab[(kr + 4) * ASTRIDE + m0]);
                af[mi][3] = __float_as_uint(Ab[(kr + 4) * ASTRIDE + m0 + 8]);
            }
            uint32_t bf[8][2];
            #pragma unroll
            for (int nj = 0; nj < 8; nj++) {
                int n0 = nq * 64 + nj * 8 + q;
                bf[nj][0] = __float_as_uint(Bb[kr * ASTRIDE + n0]);
                bf[nj][1] = __float_as_uint(Bb[(kr + 4) * ASTRIDE + n0]);
            }
            #pragma unroll
            for (int mi = 0; mi < 2; mi++)
                #pragma unroll
                for (int nj = 0; nj < 8; nj++)
                    mma_tf32(acc[mi][nj], af[mi][0], af[mi][1], af[mi][2], af[mi][3],
                             bf[nj][0], bf[nj][1]);
        }
        __syncthreads();
        if (i + 2 < NCHUNK) { produce(i + 2); CP_COMMIT(); }
    }

    // epilogue
    #pragma unroll
    for (int mi = 0; mi < 2; mi++) {
        #pragma unroll
        for (int nj = 0; nj < 8; nj++) {
            int o = bo + nq * 64 + nj * 8 + 2 * c2;
            #pragma unroll
            for (int half = 0; half < 2; half++) {
                int m = mq * 32 + mi * 16 + q + half * 8;
                int s = mt * 128 + m;
                int h = s >> 6, w = s & 63;
                size_t base = (((size_t)b * CO + o) * HH + h) * WW + w;
                out[base]        = acc[mi][nj][half * 2];
                out[base + 4096] = acc[mi][nj][half * 2 + 1];   // o+1
            }
        }
    }
}

// ---------------- launch ----------------
extern "C" void kernel_launch(void* const* d_in, const int* in_sizes, int n_in,
                              void* d_out, int out_size)
{
    const float* x     = (const float*)d_in[0];
    const float* off_w = (const float*)d_in[1];
    const float* off_b = (const float*)d_in[2];
    const float* mod_w = (const float*)d_in[3];
    const float* mod_b = (const float*)d_in[4];
    const float* reg_w = (const float*)d_in[5];
    float* out = (float*)d_out;

    cudaFuncSetAttribute(k_gemm, cudaFuncAttributeMaxDynamicSharedMemorySize, GEMM_SMEM);

    k_prep<<<(CK*CO + 255) / 256, 256>>>(reg_w, off_w, mod_w);
    dim3 g1(16, 8);
    k_off<<<g1, 256>>>(x, off_b, mod_b);
    dim3 g2(16, 2, 8);
    k_gather<<<g2, 256>>>(x);
    dim3 g3(32, 2, 8);
    k_gemm<<<g3, 256, GEMM_SMEM>>>(out);
}